// round 10
// baseline (speedup 1.0000x reference)
#include <cuda_runtime.h>
#include <float.h>

#define W    512
#define H    512
#define PW   508          // W - 5 + 1
#define NIMG 128
#define NT   6
#define STRIP 127
#define NSTRIP 4          // 4 * 127 = 508

// Per-image, per-row running argmax of the 5x5 window-sum map.
__device__ float g_rowmax[NIMG * 512];
__device__ int   g_rowarg[NIMG * 512];

__device__ __forceinline__ void argmax_combine(float& v, int& i, float ov, int oi) {
    if (ov > v || (ov == v && oi < i)) { v = ov; i = oi; }
}

// ---------------------------------------------------------------------------
// Kernel 1: one full pass. For every agg row r, (max, argcol) of the 5x5
// window sums. Vertical 5-row window in registers (column == tid).
// Canonical summation order (must match kernel 2):
//   vsum = hm[r]+hm[r+1]+hm[r+2]+hm[r+3]+hm[r+4]   (per column)
//   agg  = vs[c]+vs[c+1]+vs[c+2]+vs[c+3]+vs[c+4]
// ---------------------------------------------------------------------------
__global__ __launch_bounds__(512) void k1_rowmax(const float* __restrict__ hm) {
    const int strip = blockIdx.x;
    const int img   = blockIdx.y;
    const int tid   = threadIdx.x;
    const int lane  = tid & 31;
    const int warp  = tid >> 5;
    const float* __restrict__ im = hm + (size_t)img * H * W;

    const int r0 = strip * STRIP;
    const int r1 = min(r0 + STRIP, PW);

    __shared__ float vs[W];
    __shared__ float redv[16];
    __shared__ int   redi[16];

    float b0 = im[(size_t)(r0 + 0) * W + tid];
    float b1 = im[(size_t)(r0 + 1) * W + tid];
    float b2 = im[(size_t)(r0 + 2) * W + tid];
    float b3 = im[(size_t)(r0 + 3) * W + tid];
    float b4 = im[(size_t)(r0 + 4) * W + tid];

    for (int r = r0; r < r1; ++r) {
        vs[tid] = b0 + b1 + b2 + b3 + b4;
        __syncthreads();                       // S1: vs ready

        float a  = -FLT_MAX;
        int   ai = tid;
        if (tid < PW)
            a = vs[tid] + vs[tid + 1] + vs[tid + 2] + vs[tid + 3] + vs[tid + 4];

        #pragma unroll
        for (int off = 16; off; off >>= 1) {
            float ov = __shfl_down_sync(0xffffffffu, a, off);
            int   oi = __shfl_down_sync(0xffffffffu, ai, off);
            argmax_combine(a, ai, ov, oi);
        }
        if (lane == 0) { redv[warp] = a; redi[warp] = ai; }
        __syncthreads();                       // S2: redv ready; guards vs reuse

        if (warp == 0) {
            float c  = (lane < 16) ? redv[lane] : -FLT_MAX;
            int   ci = (lane < 16) ? redi[lane] : 0x7fffffff;
            #pragma unroll
            for (int off = 8; off; off >>= 1) {
                float ov = __shfl_down_sync(0xffffffffu, c, off);
                int   oi = __shfl_down_sync(0xffffffffu, ci, off);
                argmax_combine(c, ci, ov, oi);
            }
            if (lane == 0) {
                g_rowmax[img * 512 + r] = c;
                g_rowarg[img * 512 + r] = ci;
            }
        }

        if (r + 1 < r1) {
            b0 = b1; b1 = b2; b2 = b3; b3 = b4;
            b4 = im[(size_t)(r + 5) * W + tid];
        }
    }
}

// ---------------------------------------------------------------------------
// Kernel 2: one block per image. 6 iterations:
//   (1) block argmax over 508 row maxima -> (r*, c*), emit coords (as float!)
//   (2) record (r*, c*) in the zero-box list (emulates dynamic_update_slice)
//   (3) recompute the <=9 affected agg rows with all boxes masked,
//       refresh their (max, argcol) entries
// ---------------------------------------------------------------------------
__global__ __launch_bounds__(512) void k2_iter(const float* __restrict__ hm,
                                               float* __restrict__ out) {
    const int img  = blockIdx.x;
    const int tid  = threadIdx.x;
    const int lane = tid & 31;
    const int warp = tid >> 5;
    const float* __restrict__ im = hm + (size_t)img * H * W;

    __shared__ float s_max[512];
    __shared__ int   s_arg[512];
    __shared__ float s_vs[9][W];
    __shared__ int   s_boxr[NT], s_boxc[NT];
    __shared__ float redv[16];
    __shared__ int   redi[16];

    s_max[tid] = (tid < PW) ? g_rowmax[img * 512 + tid] : -FLT_MAX;
    s_arg[tid] = (tid < PW) ? g_rowarg[img * 512 + tid] : 0;
    __syncthreads();

    for (int t = 0; t < NT; ++t) {
        // ---- global argmax over row maxima (tie: smaller row) ----
        float a  = s_max[tid];
        int   ai = tid;
        #pragma unroll
        for (int off = 16; off; off >>= 1) {
            float ov = __shfl_down_sync(0xffffffffu, a, off);
            int   oi = __shfl_down_sync(0xffffffffu, ai, off);
            argmax_combine(a, ai, ov, oi);
        }
        if (lane == 0) { redv[warp] = a; redi[warp] = ai; }
        __syncthreads();
        if (warp == 0) {
            float b  = (lane < 16) ? redv[lane] : -FLT_MAX;
            int   bi = (lane < 16) ? redi[lane] : 0x7fffffff;
            #pragma unroll
            for (int off = 8; off; off >>= 1) {
                float ov = __shfl_down_sync(0xffffffffu, b, off);
                int   oi = __shfl_down_sync(0xffffffffu, bi, off);
                argmax_combine(b, bi, ov, oi);
            }
            if (lane == 0) {
                const int br = bi;
                const int bc = s_arg[bi];
                s_boxr[t] = br;
                s_boxc[t] = bc;
                // SWAP_RC: output row is [col + RADIUS, row + RADIUS], as fp32
                out[img * NT * 2 + t * 2 + 0] = (float)(bc + 2);
                out[img * NT * 2 + t * 2 + 1] = (float)(br + 2);
            }
        }
        __syncthreads();
        if (t == NT - 1) break;          // no repair needed after last pick

        // ---- recompute affected rows with zero-box mask ----
        const int rs = s_boxr[t];
        const int rlo = max(0, rs - 4);
        const int rhi = min(PW - 1, rs + 4);
        const int nrows = rhi - rlo + 1;     // <= 9
        const int nyr   = nrows + 4;         // <= 13 input rows

        float vals[13];
        #pragma unroll
        for (int j = 0; j < 13; ++j) {
            float v = 0.f;
            if (j < nyr) {
                const int y = rlo + j;
                v = im[(size_t)y * W + tid];
                for (int b = 0; b <= t; ++b) {
                    if ((unsigned)(y - s_boxr[b]) < 5u &&
                        (unsigned)(tid - s_boxc[b]) < 5u)
                        v = 0.f;
                }
            }
            vals[j] = v;
        }
        for (int k = 0; k < nrows; ++k)
            s_vs[k][tid] = vals[k] + vals[k + 1] + vals[k + 2]
                         + vals[k + 3] + vals[k + 4];
        __syncthreads();

        if (warp < nrows) {
            const int rr = rlo + warp;
            float best = -FLT_MAX;
            int   bidx = 0x7fffffff;
            for (int c = lane; c < PW; c += 32) {
                const float av = s_vs[warp][c] + s_vs[warp][c + 1] + s_vs[warp][c + 2]
                               + s_vs[warp][c + 3] + s_vs[warp][c + 4];
                if (av > best) { best = av; bidx = c; }   // strict > : first occurrence
            }
            #pragma unroll
            for (int off = 16; off; off >>= 1) {
                float ov = __shfl_down_sync(0xffffffffu, best, off);
                int   oi = __shfl_down_sync(0xffffffffu, bidx, off);
                argmax_combine(best, bidx, ov, oi);
            }
            if (lane == 0) { s_max[rr] = best; s_arg[rr] = bidx; }
        }
        __syncthreads();
    }
}

extern "C" void kernel_launch(void* const* d_in, const int* in_sizes, int n_in,
                              void* d_out, int out_size) {
    const float* hm = (const float*)d_in[0];
    float* out = (float*)d_out;
    (void)in_sizes; (void)n_in; (void)out_size;

    dim3 g1(NSTRIP, NIMG);
    k1_rowmax<<<g1, 512>>>(hm);
    k2_iter<<<NIMG, 512>>>(hm, out);
}

// round 13
// speedup vs baseline: 1.5672x; 1.5672x over previous
#include <cuda_runtime.h>
#include <float.h>

#define W    512
#define H    512
#define PW   508          // W - 5 + 1
#define NIMG 128
#define NT   6

// Per-image, per-row running argmax of the 5x5 window-sum map.
__device__ float g_rowmax[NIMG * 512];
__device__ int   g_rowarg[NIMG * 512];

__device__ __forceinline__ void argmax_combine(float& v, int& i, float ov, int oi) {
    if (ov > v || (ov == v && oi < i)) { v = ov; i = oi; }
}

// ---------------------------------------------------------------------------
// Kernel 1 (barrier-free, warp-per-row): warp handles one agg row r.
// Lane l owns columns [16l, 16l+16). Vertical 5-row sum accumulated in
// registers in canonical order b0+b1+b2+b3+b4 (left-assoc); horizontal window
// sum vs[c]+vs[c+1]+vs[c+2]+vs[c+3]+vs[c+4] (left-assoc) — must match k2.
// Neighbor columns 16l+16..16l+19 fetched via shfl_down from lane l+1.
// ---------------------------------------------------------------------------
__global__ __launch_bounds__(256) void k1_rowmax(const float* __restrict__ hm) {
    const int lane = threadIdx.x & 31;
    const int warp = threadIdx.x >> 5;
    const int r    = blockIdx.x * 8 + warp;       // 64 x-blocks * 8 warps = 512 rows
    const int img  = blockIdx.y;
    if (r >= PW) return;                          // uniform per warp; no barriers used

    const float* __restrict__ im = hm + (size_t)img * H * W;

    // vertical sums for 16 owned columns, accumulated row-by-row (left-assoc)
    float a[16];
    {
        const float4* p = (const float4*)(im + (size_t)r * W) + lane * 4;
        float4 v0 = p[0], v1 = p[1], v2 = p[2], v3 = p[3];
        a[0]=v0.x; a[1]=v0.y; a[2]=v0.z; a[3]=v0.w;
        a[4]=v1.x; a[5]=v1.y; a[6]=v1.z; a[7]=v1.w;
        a[8]=v2.x; a[9]=v2.y; a[10]=v2.z; a[11]=v2.w;
        a[12]=v3.x; a[13]=v3.y; a[14]=v3.z; a[15]=v3.w;
    }
    #pragma unroll
    for (int dy = 1; dy < 5; ++dy) {
        const float4* p = (const float4*)(im + (size_t)(r + dy) * W) + lane * 4;
        float4 v0 = p[0], v1 = p[1], v2 = p[2], v3 = p[3];
        a[0]+=v0.x; a[1]+=v0.y; a[2]+=v0.z; a[3]+=v0.w;
        a[4]+=v1.x; a[5]+=v1.y; a[6]+=v1.z; a[7]+=v1.w;
        a[8]+=v2.x; a[9]+=v2.y; a[10]+=v2.z; a[11]+=v2.w;
        a[12]+=v3.x; a[13]+=v3.y; a[14]+=v3.z; a[15]+=v3.w;
    }

    // columns 16l+16..16l+19 = next lane's a[0..3]
    float ext[4];
    ext[0] = __shfl_down_sync(0xffffffffu, a[0], 1);
    ext[1] = __shfl_down_sync(0xffffffffu, a[1], 1);
    ext[2] = __shfl_down_sync(0xffffffffu, a[2], 1);
    ext[3] = __shfl_down_sync(0xffffffffu, a[3], 1);

    float av[20];
    #pragma unroll
    for (int i = 0; i < 16; ++i) av[i] = a[i];
    #pragma unroll
    for (int i = 0; i < 4; ++i)  av[16 + i] = ext[i];

    // 16 window sums; local argmax (ascending k + strict > == first occurrence)
    float best = -FLT_MAX;
    int   bcol = 0x7fffffff;
    #pragma unroll
    for (int k = 0; k < 16; ++k) {
        const float w = av[k] + av[k + 1] + av[k + 2] + av[k + 3] + av[k + 4];
        const int   c = lane * 16 + k;
        if (c < PW && w > best) { best = w; bcol = c; }
    }

    // warp argmax (tie: smaller column)
    #pragma unroll
    for (int off = 16; off; off >>= 1) {
        float ov = __shfl_down_sync(0xffffffffu, best, off);
        int   oi = __shfl_down_sync(0xffffffffu, bcol, off);
        argmax_combine(best, bcol, ov, oi);
    }
    if (lane == 0) {
        g_rowmax[img * 512 + r] = best;
        g_rowarg[img * 512 + r] = bcol;
    }
}

// ---------------------------------------------------------------------------
// Kernel 2: one block per image. 6 iterations:
//   (1) block argmax over 508 row maxima -> (r*, c*), emit coords (fp32)
//   (2) record (r*, c*) in the zero-box list (emulates dynamic_update_slice)
//   (3) recompute the <=9 affected agg rows with all boxes masked,
//       refresh their (max, argcol) entries
// (unchanged from the passing Round-10 kernel)
// ---------------------------------------------------------------------------
__global__ __launch_bounds__(512) void k2_iter(const float* __restrict__ hm,
                                               float* __restrict__ out) {
    const int img  = blockIdx.x;
    const int tid  = threadIdx.x;
    const int lane = tid & 31;
    const int warp = tid >> 5;
    const float* __restrict__ im = hm + (size_t)img * H * W;

    __shared__ float s_max[512];
    __shared__ int   s_arg[512];
    __shared__ float s_vs[9][W];
    __shared__ int   s_boxr[NT], s_boxc[NT];
    __shared__ float redv[16];
    __shared__ int   redi[16];

    s_max[tid] = (tid < PW) ? g_rowmax[img * 512 + tid] : -FLT_MAX;
    s_arg[tid] = (tid < PW) ? g_rowarg[img * 512 + tid] : 0;
    __syncthreads();

    for (int t = 0; t < NT; ++t) {
        // ---- global argmax over row maxima (tie: smaller row) ----
        float a  = s_max[tid];
        int   ai = tid;
        #pragma unroll
        for (int off = 16; off; off >>= 1) {
            float ov = __shfl_down_sync(0xffffffffu, a, off);
            int   oi = __shfl_down_sync(0xffffffffu, ai, off);
            argmax_combine(a, ai, ov, oi);
        }
        if (lane == 0) { redv[warp] = a; redi[warp] = ai; }
        __syncthreads();
        if (warp == 0) {
            float b  = (lane < 16) ? redv[lane] : -FLT_MAX;
            int   bi = (lane < 16) ? redi[lane] : 0x7fffffff;
            #pragma unroll
            for (int off = 8; off; off >>= 1) {
                float ov = __shfl_down_sync(0xffffffffu, b, off);
                int   oi = __shfl_down_sync(0xffffffffu, bi, off);
                argmax_combine(b, bi, ov, oi);
            }
            if (lane == 0) {
                const int br = bi;
                const int bc = s_arg[bi];
                s_boxr[t] = br;
                s_boxc[t] = bc;
                // SWAP_RC: output row is [col + RADIUS, row + RADIUS], as fp32
                out[img * NT * 2 + t * 2 + 0] = (float)(bc + 2);
                out[img * NT * 2 + t * 2 + 1] = (float)(br + 2);
            }
        }
        __syncthreads();
        if (t == NT - 1) break;          // no repair needed after last pick

        // ---- recompute affected rows with zero-box mask ----
        const int rs = s_boxr[t];
        const int rlo = max(0, rs - 4);
        const int rhi = min(PW - 1, rs + 4);
        const int nrows = rhi - rlo + 1;     // <= 9
        const int nyr   = nrows + 4;         // <= 13 input rows

        float vals[13];
        #pragma unroll
        for (int j = 0; j < 13; ++j) {
            float v = 0.f;
            if (j < nyr) {
                const int y = rlo + j;
                v = im[(size_t)y * W + tid];
                for (int b = 0; b <= t; ++b) {
                    if ((unsigned)(y - s_boxr[b]) < 5u &&
                        (unsigned)(tid - s_boxc[b]) < 5u)
                        v = 0.f;
                }
            }
            vals[j] = v;
        }
        for (int k = 0; k < nrows; ++k)
            s_vs[k][tid] = vals[k] + vals[k + 1] + vals[k + 2]
                         + vals[k + 3] + vals[k + 4];
        __syncthreads();

        if (warp < nrows) {
            const int rr = rlo + warp;
            float best = -FLT_MAX;
            int   bidx = 0x7fffffff;
            for (int c = lane; c < PW; c += 32) {
                const float av = s_vs[warp][c] + s_vs[warp][c + 1] + s_vs[warp][c + 2]
                               + s_vs[warp][c + 3] + s_vs[warp][c + 4];
                if (av > best) { best = av; bidx = c; }   // strict > : first occurrence
            }
            #pragma unroll
            for (int off = 16; off; off >>= 1) {
                float ov = __shfl_down_sync(0xffffffffu, best, off);
                int   oi = __shfl_down_sync(0xffffffffu, bidx, off);
                argmax_combine(best, bidx, ov, oi);
            }
            if (lane == 0) { s_max[rr] = best; s_arg[rr] = bidx; }
        }
        __syncthreads();
    }
}

extern "C" void kernel_launch(void* const* d_in, const int* in_sizes, int n_in,
                              void* d_out, int out_size) {
    const float* hm = (const float*)d_in[0];
    float* out = (float*)d_out;
    (void)in_sizes; (void)n_in; (void)out_size;

    dim3 g1(64, NIMG);                 // 64 blocks * 8 warps = 512 rows (>= 508)
    k1_rowmax<<<g1, 256>>>(hm);
    k2_iter<<<NIMG, 512>>>(hm, out);
}